// round 4
// baseline (speedup 1.0000x reference)
#include <cuda_runtime.h>
#include <cstdint>

#define NSIZE 4096
#define BVAL 8
#define CVAL 32

// Scratch: E[b,n] = exp(mean_c x[b,c,n])
__device__ float g_E[BVAL * NSIZE];

// ---------------------------------------------------------------------------
// Kernel 1: channel-mean + exp.  B*N = 32768 threads, each reduces 32 strided
// floats (coalesced across threads), writes exp(mean).
// ---------------------------------------------------------------------------
__global__ void reduce_exp_kernel(const float* __restrict__ x) {
    int idx = blockIdx.x * blockDim.x + threadIdx.x;   // idx = b*N + n
    if (idx >= BVAL * NSIZE) return;
    int b = idx >> 12;
    int n = idx & (NSIZE - 1);
    const float* xp = x + (size_t)b * CVAL * NSIZE + n;
    float s = 0.0f;
#pragma unroll
    for (int c = 0; c < CVAL; c++) s += xp[(size_t)c * NSIZE];
    g_E[idx] = __expf(s * (1.0f / CVAL));
}

// ---------------------------------------------------------------------------
// Kernel 2: fused weight-generation + einsum + para*relu epilogue.
//   out[b,c,m] = relu( para[c,m] * sum_n fea[b,c,n] * adj[n,m] * g(n,m) )
//   g(n,m) = 2*min(Em,En)/(Em+En)  ==  1 - |tanh((ca_m-ca_n)/2)|
//         ==  2*| |sigmoid(ca_m-ca_n)-0.5| - 0.5 |   (exact, already symmetric)
// One block = one (b, 128-column m-tile).  1 thread per m column,
// 16 packed f32x2 accumulators over the C=32 channels.
// ---------------------------------------------------------------------------
__global__ void __launch_bounds__(128, 2) gcn_main_kernel(
    const float* __restrict__ x,
    const float* __restrict__ para,
    const float* __restrict__ adj,
    float* __restrict__ out)
{
    // fea chunk: [n_local][c], row padded to 34 floats (136B: 8B-aligned for
    // LDS.64, and stride-34 avoids 32-way STS bank conflicts on the fill).
    __shared__ __align__(16) float fea_s[128][34];
    __shared__ float en_s[128];

    const int tid = threadIdx.x;
    const int b   = blockIdx.y;
    const int m   = blockIdx.x * 128 + tid;

    const float em = g_E[(b << 12) + m];

    unsigned long long acc[16];
#pragma unroll
    for (int i = 0; i < 16; i++) acc[i] = 0ull;   // {0.0f, 0.0f}

    const float* xb = x + (size_t)b * CVAL * NSIZE;

    for (int n0 = 0; n0 < NSIZE; n0 += 128) {
        __syncthreads();
        {
            // Thread tid owns n_local = tid; loop over c (coalesced LDG,
            // conflict-benign STS thanks to the 34-float row stride).
            const float* xp = xb + n0 + tid;
#pragma unroll
            for (int c = 0; c < CVAL; c++)
                fea_s[tid][c] = xp[(size_t)c * NSIZE];
            en_s[tid] = g_E[(b << 12) + n0 + tid];
        }
        __syncthreads();

        const float* adjp = adj + (size_t)n0 * NSIZE + m;
#pragma unroll 8
        for (int nl = 0; nl < 128; nl++) {
            float a  = adjp[(size_t)nl * NSIZE];     // coalesced, L2-resident
            float en = en_s[nl];                     // broadcast LDS
            // g = 2*min(Em,En)/(Em+En)  (exact closed form of ref weight)
            float w  = a * __fdividef(2.0f * fminf(em, en), em + en);

            unsigned long long w2;
            unsigned int wi = __float_as_uint(w);
            asm("mov.b64 %0, {%1, %1};" : "=l"(w2) : "r"(wi));

            const unsigned long long* fp =
                reinterpret_cast<const unsigned long long*>(fea_s[nl]);
#pragma unroll
            for (int i = 0; i < 16; i++)
                asm("fma.rn.f32x2 %0, %1, %2, %0;"   // packed FFMA2: 2 ch/inst
                    : "+l"(acc[i]) : "l"(fp[i]), "l"(w2));
        }
    }

    // Epilogue: *para, relu, store (coalesced across threads per channel).
    float* outp = out + (size_t)b * CVAL * NSIZE + m;
#pragma unroll
    for (int i = 0; i < 16; i++) {
        unsigned int lo, hi;
        asm("mov.b64 {%0, %1}, %2;" : "=r"(lo), "=r"(hi) : "l"(acc[i]));
        int c0 = 2 * i, c1 = 2 * i + 1;
        float v0 = __uint_as_float(lo) * para[(size_t)c0 * NSIZE + m];
        float v1 = __uint_as_float(hi) * para[(size_t)c1 * NSIZE + m];
        outp[(size_t)c0 * NSIZE] = fmaxf(v0, 0.0f);
        outp[(size_t)c1 * NSIZE] = fmaxf(v1, 0.0f);
    }
}

// ---------------------------------------------------------------------------
extern "C" void kernel_launch(void* const* d_in, const int* in_sizes, int n_in,
                              void* d_out, int out_size) {
    const float* x    = (const float*)d_in[0];   // [8,32,64,64]
    const float* para = (const float*)d_in[1];   // [1,32,64,64]
    const float* adj  = (const float*)d_in[2];   // [4096,4096]
    float*       out  = (float*)d_out;           // [8,32,64,64]

    (void)in_sizes; (void)n_in; (void)out_size;

    reduce_exp_kernel<<<(BVAL * NSIZE + 255) / 256, 256>>>(x);

    dim3 grid(NSIZE / 128, BVAL);
    gcn_main_kernel<<<grid, 128>>>(x, para, adj, out);
}

// round 5
// speedup vs baseline: 1.4452x; 1.4452x over previous
#include <cuda_runtime.h>
#include <cstdint>

#define NSIZE  4096
#define BVAL   8
#define CVAL   32
#define KSPLIT 2
#define KHALF  (NSIZE / KSPLIT)   // 2048
#define MTILE  256                // m columns per block (2 per thread)

// Scratch: E[b,n] = exp(mean_c x[b,c,n]); K-split partial sums.
__device__ float g_E[BVAL * NSIZE];
__device__ float g_partial[KSPLIT][BVAL][CVAL][NSIZE];   // 8 MB

// ---------------------------------------------------------------------------
// Kernel 1: channel-mean + exp.
// ---------------------------------------------------------------------------
__global__ void reduce_exp_kernel(const float* __restrict__ x) {
    int idx = blockIdx.x * blockDim.x + threadIdx.x;   // idx = b*N + n
    if (idx >= BVAL * NSIZE) return;
    int b = idx >> 12;
    int n = idx & (NSIZE - 1);
    const float* xp = x + (size_t)b * CVAL * NSIZE + n;
    float s = 0.0f;
#pragma unroll
    for (int c = 0; c < CVAL; c++) s += xp[(size_t)c * NSIZE];
    g_E[idx] = __expf(s * (1.0f / CVAL));
}

// ---------------------------------------------------------------------------
// Kernel 2: fused weight-gen + einsum, K-split partials (no epilogue here).
//   partial[ks][b][c][m] = sum_{n in half ks} fea[b,c,n]*adj[n,m]*g(n,m)/2
//   g(n,m)/2 = min(Em,En)/(Em+En)   (x2 restored in the epilogue kernel)
// One block = (b, 256-col m-tile, K-half). 128 threads, 2 m per thread,
// 32 packed f32x2 accumulators (all 32 channels x 2 columns).
// ---------------------------------------------------------------------------
__global__ void __launch_bounds__(128, 2) gcn_main_kernel(
    const float* __restrict__ x,
    const float* __restrict__ adj)
{
    // fea chunk [n_local][c], row stride 36 floats (144B: 16B-aligned for
    // LDS.128; fill has only a 4-way STS conflict).
    __shared__ __align__(16) float fea_s[128][36];
    __shared__ float en_s[128];

    const int tid = threadIdx.x;
    const int b   = blockIdx.y;
    const int ks  = blockIdx.z;
    const int m0  = blockIdx.x * MTILE + tid;
    const int m1  = m0 + 128;

    const float em0 = g_E[(b << 12) + m0];
    const float em1 = g_E[(b << 12) + m1];

    unsigned long long acc0[16], acc1[16];
#pragma unroll
    for (int i = 0; i < 16; i++) { acc0[i] = 0ull; acc1[i] = 0ull; }

    const float* xb   = x + (size_t)b * CVAL * NSIZE;
    const int    nbeg = ks * KHALF;

    for (int n0 = nbeg; n0 < nbeg + KHALF; n0 += 128) {
        __syncthreads();
        {
            const float* xp = xb + n0 + tid;          // coalesced over tid
#pragma unroll
            for (int c = 0; c < CVAL; c++)
                fea_s[tid][c] = xp[(size_t)c * NSIZE];
            en_s[tid] = g_E[(b << 12) + n0 + tid];
        }
        __syncthreads();

        const float* adjp = adj + (size_t)n0 * NSIZE;
#pragma unroll 4
        for (int nl = 0; nl < 128; nl++) {
            float a0 = adjp[(size_t)nl * NSIZE + m0]; // coalesced, L2-hot
            float a1 = adjp[(size_t)nl * NSIZE + m1];
            float en = en_s[nl];                      // broadcast LDS

            float r0, r1;
            asm("rcp.approx.f32 %0, %1;" : "=f"(r0) : "f"(em0 + en));
            asm("rcp.approx.f32 %0, %1;" : "=f"(r1) : "f"(em1 + en));
            float w0 = a0 * fminf(em0, en) * r0;      // = adj * g/2
            float w1 = a1 * fminf(em1, en) * r1;

            unsigned long long w20, w21;
            unsigned int wi0 = __float_as_uint(w0), wi1 = __float_as_uint(w1);
            asm("mov.b64 %0, {%1, %1};" : "=l"(w20) : "r"(wi0));
            asm("mov.b64 %0, {%1, %1};" : "=l"(w21) : "r"(wi1));

            const ulonglong2* fp =
                reinterpret_cast<const ulonglong2*>(&fea_s[nl][0]);
#pragma unroll
            for (int i = 0; i < 8; i++) {
                ulonglong2 f = fp[i];                 // LDS.128 broadcast
                asm("fma.rn.f32x2 %0, %1, %2, %0;" : "+l"(acc0[2*i  ]) : "l"(f.x), "l"(w20));
                asm("fma.rn.f32x2 %0, %1, %2, %0;" : "+l"(acc0[2*i+1]) : "l"(f.y), "l"(w20));
                asm("fma.rn.f32x2 %0, %1, %2, %0;" : "+l"(acc1[2*i  ]) : "l"(f.x), "l"(w21));
                asm("fma.rn.f32x2 %0, %1, %2, %0;" : "+l"(acc1[2*i+1]) : "l"(f.y), "l"(w21));
            }
        }
    }

    // Store partials (exclusive region per block, no atomics).
    float* pp = &g_partial[ks][b][0][0];
#pragma unroll
    for (int i = 0; i < 16; i++) {
        unsigned int lo, hi;
        int c0 = 2 * i, c1 = 2 * i + 1;
        asm("mov.b64 {%0, %1}, %2;" : "=r"(lo), "=r"(hi) : "l"(acc0[i]));
        pp[(size_t)c0 * NSIZE + m0] = __uint_as_float(lo);
        pp[(size_t)c1 * NSIZE + m0] = __uint_as_float(hi);
        asm("mov.b64 {%0, %1}, %2;" : "=r"(lo), "=r"(hi) : "l"(acc1[i]));
        pp[(size_t)c0 * NSIZE + m1] = __uint_as_float(lo);
        pp[(size_t)c1 * NSIZE + m1] = __uint_as_float(hi);
    }
}

// ---------------------------------------------------------------------------
// Kernel 3: combine K-halves + para * relu epilogue (restores the x2).
// ---------------------------------------------------------------------------
__global__ void epilogue_kernel(const float* __restrict__ para,
                                float* __restrict__ out) {
    int idx = blockIdx.x * blockDim.x + threadIdx.x;   // b*C*N + c*N + m
    if (idx >= BVAL * CVAL * NSIZE) return;
    int b    = idx >> 17;                // C*N = 131072 = 2^17
    int rest = idx & (CVAL * NSIZE - 1); // = c*N + m == para index
    float v = g_partial[0][b][0][rest] + g_partial[1][b][0][rest];
    out[idx] = fmaxf(2.0f * v * para[rest], 0.0f);
}

// ---------------------------------------------------------------------------
extern "C" void kernel_launch(void* const* d_in, const int* in_sizes, int n_in,
                              void* d_out, int out_size) {
    const float* x    = (const float*)d_in[0];   // [8,32,64,64]
    const float* para = (const float*)d_in[1];   // [1,32,64,64]
    const float* adj  = (const float*)d_in[2];   // [4096,4096]
    float*       out  = (float*)d_out;           // [8,32,64,64]

    (void)in_sizes; (void)n_in; (void)out_size;

    reduce_exp_kernel<<<(BVAL * NSIZE + 255) / 256, 256>>>(x);

    dim3 grid(NSIZE / MTILE, BVAL, KSPLIT);      // 16 x 8 x 2 = 256 blocks
    gcn_main_kernel<<<grid, 128>>>(x, adj);

    epilogue_kernel<<<(BVAL * CVAL * NSIZE + 255) / 256, 256>>>(para, out);
}

// round 9
// speedup vs baseline: 1.8233x; 1.2616x over previous
#include <cuda_runtime.h>
#include <cstdint>

#define NSIZE  4096
#define BVAL   8
#define CVAL   32
#define KSPLIT 8
#define KCH    (NSIZE / KSPLIT)   // 512 n per block
#define MTILE  512                // m columns per block (2 per thread, 256 thr)

// Scratch: E[b,n] = exp(mean_c x[b,c,n]); K-split partial sums (32 MB).
__device__ float g_E[BVAL * NSIZE];
__device__ float g_partial[KSPLIT][BVAL][CVAL][NSIZE];

// ---------------------------------------------------------------------------
// Kernel 1: channel-mean + exp, 4 n per thread via float4 (MLP=32 LDG.128).
// ---------------------------------------------------------------------------
__global__ void reduce_exp_kernel(const float* __restrict__ x) {
    int t = blockIdx.x * blockDim.x + threadIdx.x;      // t in [0, B*N/4)
    if (t >= BVAL * NSIZE / 4) return;
    int b  = t >> 10;                                   // N/4 = 1024 per b
    int n4 = (t & 1023) << 2;
    const float4* xp = (const float4*)(x + (size_t)b * CVAL * NSIZE + n4);
    float4 s = make_float4(0.f, 0.f, 0.f, 0.f);
#pragma unroll
    for (int c = 0; c < CVAL; c++) {
        float4 v = xp[(size_t)c * (NSIZE / 4)];
        s.x += v.x; s.y += v.y; s.z += v.z; s.w += v.w;
    }
    const float inv = 1.0f / CVAL;
    float4 e = make_float4(__expf(s.x * inv), __expf(s.y * inv),
                           __expf(s.z * inv), __expf(s.w * inv));
    *(float4*)(g_E + (b << 12) + n4) = e;
}

// ---------------------------------------------------------------------------
// Kernel 2: fused weight-gen + einsum, K-split partials.
//   partial[ks][b][c][m] = sum_{n in chunk ks} fea[b,c,n]*adj[n,m]*g(n,m)/2
//   g(n,m)/2 = min(Em,En)/(Em+En)   (exact closed form; x2 in epilogue)
// 256 threads, 2 m per thread, 32 f32x2 accumulators; adj register-prefetched
// in chunks of 4 n so the L2 round trip overlaps the FFMA2 stream.
// ---------------------------------------------------------------------------
__global__ void __launch_bounds__(256, 2) gcn_main_kernel(
    const float* __restrict__ x,
    const float* __restrict__ adj)
{
    // fea chunk [n_local][c], row stride 36 floats (144B, 16B-aligned LDS.128)
    __shared__ __align__(16) float fea_s[128][36];
    __shared__ float en_s[128];

    const int tid = threadIdx.x;
    const int b   = blockIdx.y;
    const int ks  = blockIdx.z;
    const int m0  = blockIdx.x * MTILE + tid;
    const int m1  = m0 + 256;

    const float em0 = g_E[(b << 12) + m0];
    const float em1 = g_E[(b << 12) + m1];

    unsigned long long acc0[16], acc1[16];
#pragma unroll
    for (int i = 0; i < 16; i++) { acc0[i] = 0ull; acc1[i] = 0ull; }

    const float* xb   = x + (size_t)b * CVAL * NSIZE;
    const int    nbeg = ks * KCH;

    for (int n0 = nbeg; n0 < nbeg + KCH; n0 += 128) {
        __syncthreads();
        {
            // 256 threads fill 128 rows x 32 ch: low half ch 0-15, high 16-31.
            const int nloc = tid & 127;
            const int ch   = (tid >> 7) << 4;
            const float* xp = xb + (size_t)ch * NSIZE + n0 + nloc;
#pragma unroll
            for (int j = 0; j < 16; j++)
                fea_s[nloc][ch + j] = xp[(size_t)j * NSIZE];
            if (tid < 128) en_s[tid] = g_E[(b << 12) + n0 + tid];
        }
        __syncthreads();

        const float* adjp = adj + (size_t)n0 * NSIZE;

        // software pipeline: prefetch 4-iteration chunks of adj (8 LDG MLP)
        float pa0[4], pa1[4];
#pragma unroll
        for (int j = 0; j < 4; j++) {
            pa0[j] = adjp[(size_t)j * NSIZE + m0];
            pa1[j] = adjp[(size_t)j * NSIZE + m1];
        }

        for (int nl = 0; nl < 128; nl += 4) {
            float ca0[4], ca1[4];
#pragma unroll
            for (int j = 0; j < 4; j++) { ca0[j] = pa0[j]; ca1[j] = pa1[j]; }

            if (nl + 4 < 128) {     // uniform branch; avoids OOB on last chunk
#pragma unroll
                for (int j = 0; j < 4; j++) {
                    pa0[j] = adjp[(size_t)(nl + 4 + j) * NSIZE + m0];
                    pa1[j] = adjp[(size_t)(nl + 4 + j) * NSIZE + m1];
                }
            }

#pragma unroll
            for (int j = 0; j < 4; j++) {
                const float en = en_s[nl + j];            // broadcast LDS
                float r0, r1;
                asm("rcp.approx.f32 %0, %1;" : "=f"(r0) : "f"(em0 + en));
                asm("rcp.approx.f32 %0, %1;" : "=f"(r1) : "f"(em1 + en));
                const float w0 = ca0[j] * fminf(em0, en) * r0;  // adj * g/2
                const float w1 = ca1[j] * fminf(em1, en) * r1;

                unsigned long long w20, w21;
                unsigned int wi0 = __float_as_uint(w0);
                unsigned int wi1 = __float_as_uint(w1);
                asm("mov.b64 %0, {%1, %1};" : "=l"(w20) : "r"(wi0));
                asm("mov.b64 %0, {%1, %1};" : "=l"(w21) : "r"(wi1));

                const ulonglong2* fp =
                    reinterpret_cast<const ulonglong2*>(&fea_s[nl + j][0]);
#pragma unroll
                for (int i = 0; i < 8; i++) {
                    ulonglong2 f = fp[i];                 // LDS.128 broadcast
                    asm("fma.rn.f32x2 %0, %1, %2, %0;" : "+l"(acc0[2*i  ]) : "l"(f.x), "l"(w20));
                    asm("fma.rn.f32x2 %0, %1, %2, %0;" : "+l"(acc0[2*i+1]) : "l"(f.y), "l"(w20));
                    asm("fma.rn.f32x2 %0, %1, %2, %0;" : "+l"(acc1[2*i  ]) : "l"(f.x), "l"(w21));
                    asm("fma.rn.f32x2 %0, %1, %2, %0;" : "+l"(acc1[2*i+1]) : "l"(f.y), "l"(w21));
                }
            }
        }
    }

    // Store partials (exclusive region per block, no atomics, coalesced).
    float* pp = &g_partial[ks][b][0][0];
#pragma unroll
    for (int i = 0; i < 16; i++) {
        unsigned int lo, hi;
        int c0 = 2 * i, c1 = 2 * i + 1;
        asm("mov.b64 {%0, %1}, %2;" : "=r"(lo), "=r"(hi) : "l"(acc0[i]));
        pp[(size_t)c0 * NSIZE + m0] = __uint_as_float(lo);
        pp[(size_t)c1 * NSIZE + m0] = __uint_as_float(hi);
        asm("mov.b64 {%0, %1}, %2;" : "=r"(lo), "=r"(hi) : "l"(acc1[i]));
        pp[(size_t)c0 * NSIZE + m1] = __uint_as_float(lo);
        pp[(size_t)c1 * NSIZE + m1] = __uint_as_float(hi);
    }
}

// ---------------------------------------------------------------------------
// Kernel 3: combine K-split partials + para * relu epilogue (restores x2).
// ---------------------------------------------------------------------------
__global__ void epilogue_kernel(const float* __restrict__ para,
                                float* __restrict__ out) {
    int idx = blockIdx.x * blockDim.x + threadIdx.x;   // b*C*N + c*N + m
    if (idx >= BVAL * CVAL * NSIZE) return;
    int b    = idx >> 17;                 // C*N = 2^17
    int rest = idx & (CVAL * NSIZE - 1);  // = c*N + m == para index
    float v = 0.0f;
#pragma unroll
    for (int s = 0; s < KSPLIT; s++) v += g_partial[s][b][0][rest];
    out[idx] = fmaxf(2.0f * v * para[rest], 0.0f);
}

// ---------------------------------------------------------------------------
extern "C" void kernel_launch(void* const* d_in, const int* in_sizes, int n_in,
                              void* d_out, int out_size) {
    const float* x    = (const float*)d_in[0];   // [8,32,64,64]
    const float* para = (const float*)d_in[1];   // [1,32,64,64]
    const float* adj  = (const float*)d_in[2];   // [4096,4096]
    float*       out  = (float*)d_out;           // [8,32,64,64]

    (void)in_sizes; (void)n_in; (void)out_size;

    reduce_exp_kernel<<<(BVAL * NSIZE / 4 + 255) / 256, 256>>>(x);

    dim3 grid(NSIZE / MTILE, BVAL, KSPLIT);      // 8 x 8 x 8 = 512 blocks
    gcn_main_kernel<<<grid, 256>>>(x, adj);

    epilogue_kernel<<<(BVAL * CVAL * NSIZE + 255) / 256, 256>>>(para, out);
}